// round 12
// baseline (speedup 1.0000x reference)
#include <cuda_runtime.h>
#include <cuda_bf16.h>
#include <cstdint>

// ---------------------------------------------------------------------------
// Problem constants
// ---------------------------------------------------------------------------
#define NO 16384
#define NU 16384
#define DK 1024
#define CNUM 51
#define NCOL 64          // g_P row stride (padded)
#define NT 7             // n-tiles of 8 cols -> 56 >= 51
#define NK32 (DK / 32)   // 32 k-blocks of 32
#define NP (NK32 / 2)    // 16 k-block PAIRS
#define GRID 256
#define NTHR 256
#define SELEM (2 * 3 * NT * 32)          // 1344 uint4 per pair-stage
#define SMEM_DYN (3 * SELEM * 16)        // 64512 B: 3-stage ring

// ---------------------------------------------------------------------------
// Device scratch (static only — no cudaMalloc allowed)
// ---------------------------------------------------------------------------
__device__ __align__(16) float g_P[(NO + NU) * NCOL];   // feat @ W^T
// Fragment-packed weights (k-PERMUTED layout matching float4 A loads):
// [K32][nt][lane] -> uint4; stride 256 uint4 per K-block (nt 0..6 used)
__device__ __align__(16) uint4 g_WbF[NK32 * 8 * 32];    // bf16(W)
__device__ __align__(16) uint4 g_WohF[NK32 * 8 * 32];   // hi(W_o)
__device__ __align__(16) uint4 g_WolF[NK32 * 8 * 32];   // lo(W_o)
__device__ int g_pred[NU];
__device__ int g_flags[NU];
__device__ float g_sum;
__device__ int g_cnt;
__device__ unsigned g_done;
// grid barrier state (generation-based; replay-safe)
__device__ volatile unsigned g_bar_count;
__device__ volatile unsigned g_bar_gen;

// ---------------------------------------------------------------------------
// Helpers
// ---------------------------------------------------------------------------
__device__ __forceinline__ uint32_t pack_bf16(float x, float y) {
    uint32_t r;
    asm("cvt.rn.bf16x2.f32 %0, %1, %2;" : "=r"(r) : "f"(y), "f"(x));
    return r;
}

__device__ __forceinline__ void mma16816(float* d, const uint32_t* a,
                                         uint32_t b0, uint32_t b1) {
    asm volatile(
        "mma.sync.aligned.m16n8k16.row.col.f32.bf16.bf16.f32 "
        "{%0,%1,%2,%3}, {%4,%5,%6,%7}, {%8,%9}, {%0,%1,%2,%3};"
        : "+f"(d[0]), "+f"(d[1]), "+f"(d[2]), "+f"(d[3])
        : "r"(a[0]), "r"(a[1]), "r"(a[2]), "r"(a[3]), "r"(b0), "r"(b1));
}

__device__ __forceinline__ uint32_t residue_pack(uint32_t hpk, float x, float y) {
    float hx = __uint_as_float(hpk << 16);
    float hy = __uint_as_float(hpk & 0xFFFF0000u);
    return pack_bf16(x - hx, y - hy);
}

__device__ __forceinline__ void cpa16(void* smem_dst, const void* gsrc) {
    uint32_t d = (uint32_t)__cvta_generic_to_shared(smem_dst);
    asm volatile("cp.async.ca.shared.global [%0], [%1], 16;" :: "r"(d), "l"(gsrc));
}
__device__ __forceinline__ void cpa_commit() {
    asm volatile("cp.async.commit_group;");
}

// Grid-wide barrier. Safe: grid (256) <= single-wave capacity (148 SMs x occ 2).
__device__ __forceinline__ void grid_sync() {
    __syncthreads();
    if (threadIdx.x == 0) {
        __threadfence();
        unsigned gen = g_bar_gen;
        unsigned t = atomicAdd((unsigned*)&g_bar_count, 1u);
        if (t == GRID - 1) {
            g_bar_count = 0;
            __threadfence();
            g_bar_gen = gen + 1;
        } else {
            while (g_bar_gen == gen) { __nanosleep(64); }
        }
        __threadfence();
    }
    __syncthreads();
}

// ---------------------------------------------------------------------------
// ONE fused kernel: convw -> sync -> GEMM(3-term classify fused, k-pair
// pipelined: ONE barrier per 2 K-blocks, 3-stage smem ring) -> sync -> epi
// ---------------------------------------------------------------------------
__global__ void __launch_bounds__(256, 2) fused_kernel(
    const float* __restrict__ feat, const float* __restrict__ b_o,
    const float* __restrict__ W, const float* __restrict__ W_o,
    const float* __restrict__ b, const int* __restrict__ label,
    const int* __restrict__ idx_m, const int* __restrict__ idx_t,
    float* __restrict__ out)
{
    extern __shared__ uint4 sB[];          // [3 stages][2 kb][3 mats][224]
    __shared__ float s_zb[64];
    __shared__ float s_wsum;
    __shared__ int s_wcnt;

    int tid = threadIdx.x;
    int wid = tid >> 5, lane = tid & 31;

    // =================== Phase 0: weight conversion (permuted-k pack) =======
    {
        int idx = blockIdx.x * NTHR + tid;   // 0..65535; use first 32768
        if (idx == 0) { g_sum = 0.f; g_cnt = 0; g_done = 0; }
        if (idx < 32768) {
            int q = idx & 3;
            int s = (idx >> 2) & 1;
            int K = (idx >> 3) & 31;
            int n = (idx >> 8) & 63;
            int mat = idx >> 14;         // 0: W, 1: W_o
            float4 f = make_float4(0.f, 0.f, 0.f, 0.f);
            if (n < CNUM) {
                const float* src = (mat == 0) ? W : W_o;
                f = *reinterpret_cast<const float4*>(
                        src + (size_t)n * DK + K * 32 + s * 16 + q * 4);
            }
            int t = ((n & 7) << 2) | q;
            int nt = n >> 3;
            size_t w32 = ((size_t)(K * 256 + nt * 32 + t) << 2) | (s << 1);
            if (mat == 0) {
                *reinterpret_cast<uint2*>(reinterpret_cast<uint32_t*>(g_WbF) + w32) =
                    make_uint2(pack_bf16(f.x, f.y), pack_bf16(f.z, f.w));
            } else {
                uint32_t h0 = pack_bf16(f.x, f.y);
                uint32_t h1 = pack_bf16(f.z, f.w);
                *reinterpret_cast<uint2*>(reinterpret_cast<uint32_t*>(g_WohF) + w32) =
                    make_uint2(h0, h1);
                *reinterpret_cast<uint2*>(reinterpret_cast<uint32_t*>(g_WolF) + w32) =
                    make_uint2(residue_pack(h0, f.x, f.y), residue_pack(h1, f.z, f.w));
            }
        }
    }
    grid_sync();

    // =================== Phase 1: GEMM + fused 3-term classification =========
    {
        bool is_u = wid < 4;
        int tile = is_u ? wid : wid - 4;
        int row0 = (is_u ? NO : 0) + blockIdx.x * 64 + tile * 16;
        int r = lane >> 2;        // 0..7
        int q = lane & 3;

        if (tid < 64) s_zb[tid] = (tid < CNUM) ? b_o[tid] : -1e30f;

        // permuted-k: each lane loads float4 at k-offset 4q (contiguous)
        const float* Ap0 = feat + (size_t)(row0 + r) * DK + 4 * q;
        const float* Ap1 = Ap0 + 8 * DK;

        // stage a k-block PAIR p into ring buffer s (1344 uint4 via cp.async)
        auto stage_pair = [&](int p, int s) {
            #pragma unroll
            for (int i0 = 0; i0 < 6; i0++) {
                int i = tid + i0 * 256;
                if (i0 == 5 && i >= SELEM) break;
                int kb = i / 672;
                int rem = i - kb * 672;
                int mat = rem / 224;
                int e = rem - mat * 224;
                const uint4* g = (mat == 0) ? g_WbF : (mat == 1) ? g_WohF : g_WolF;
                cpa16(&sB[(size_t)s * SELEM + kb * 672 + mat * 224 + e],
                      g + (2 * p + kb) * 256 + e);
            }
            cpa_commit();
        };

        stage_pair(0, 0);
        stage_pair(1, 1);

        float accP[NT][4];
        float accL[NT][4];
        #pragma unroll
        for (int nt = 0; nt < NT; nt++)
            #pragma unroll
            for (int j = 0; j < 4; j++) { accP[nt][j] = 0.f; accL[nt][j] = 0.f; }

        #pragma unroll 1
        for (int p = 0; p < NP; p++) {
            int buf = p % 3;

            if (p < NP - 1) asm volatile("cp.async.wait_group 1;");
            else            asm volatile("cp.async.wait_group 0;");
            __syncthreads();

            if (p + 2 < NP) stage_pair(p + 2, (p + 2) % 3);

            const uint4* base = sB + (size_t)buf * SELEM;

            #pragma unroll
            for (int kb = 0; kb < 2; kb++) {
                int k0 = (2 * p + kb) * 32;
                float4 v00 = *reinterpret_cast<const float4*>(Ap0 + k0);
                float4 v10 = *reinterpret_cast<const float4*>(Ap1 + k0);
                float4 v01 = *reinterpret_cast<const float4*>(Ap0 + k0 + 16);
                float4 v11 = *reinterpret_cast<const float4*>(Ap1 + k0 + 16);

                uint32_t ah0[4], ah1[4];
                ah0[0] = pack_bf16(v00.x, v00.y);
                ah0[1] = pack_bf16(v10.x, v10.y);
                ah0[2] = pack_bf16(v00.z, v00.w);
                ah0[3] = pack_bf16(v10.z, v10.w);
                ah1[0] = pack_bf16(v01.x, v01.y);
                ah1[1] = pack_bf16(v11.x, v11.y);
                ah1[2] = pack_bf16(v01.z, v01.w);
                ah1[3] = pack_bf16(v11.z, v11.w);

                const uint4* Bb = base + kb * 672 + lane;
                #pragma unroll
                for (int nt = 0; nt < NT; nt++) {
                    uint4 bb = Bb[nt * 32];
                    mma16816(accP[nt], ah0, bb.x, bb.y);
                    mma16816(accP[nt], ah1, bb.z, bb.w);
                }

                if (is_u) {
                    uint32_t al0[4], al1[4];
                    al0[0] = residue_pack(ah0[0], v00.x, v00.y);
                    al0[1] = residue_pack(ah0[1], v10.x, v10.y);
                    al0[2] = residue_pack(ah0[2], v00.z, v00.w);
                    al0[3] = residue_pack(ah0[3], v10.z, v10.w);
                    al1[0] = residue_pack(ah1[0], v01.x, v01.y);
                    al1[1] = residue_pack(ah1[1], v11.x, v11.y);
                    al1[2] = residue_pack(ah1[2], v01.z, v01.w);
                    al1[3] = residue_pack(ah1[3], v11.z, v11.w);
                    const uint4* Bh = base + kb * 672 + 224 + lane;
                    const uint4* Bl = base + kb * 672 + 448 + lane;
                    #pragma unroll
                    for (int nt = 0; nt < NT; nt++) {
                        uint4 bh = Bh[nt * 32];
                        uint4 bl = Bl[nt * 32];
                        mma16816(accL[nt], ah0, bh.x, bh.y);   // hi*hi
                        mma16816(accL[nt], ah1, bh.z, bh.w);
                        mma16816(accL[nt], al0, bh.x, bh.y);   // lo*hi
                        mma16816(accL[nt], al1, bh.z, bh.w);
                        mma16816(accL[nt], ah0, bl.x, bl.y);   // hi*lo
                        mma16816(accL[nt], ah1, bl.z, bl.w);
                    }
                }
            }
        }

        // ---- value epilogue: store P fragments (56 cols) ----
        float* dst0 = g_P + (size_t)(row0 + r) * NCOL + 2 * q;
        float* dst1 = dst0 + 8 * NCOL;
        #pragma unroll
        for (int nt = 0; nt < NT; nt++) {
            *reinterpret_cast<float2*>(dst0 + nt * 8) = make_float2(accP[nt][0], accP[nt][1]);
            *reinterpret_cast<float2*>(dst1 + nt * 8) = make_float2(accP[nt][2], accP[nt][3]);
        }

        // ---- fused classification (u-warps): rows r (A) and r+8 (B) ----
        if (is_u) {
            float mA = -1e30f, mB = -1e30f;
            int iA = 0, iB = 0;
            #pragma unroll
            for (int nt = 0; nt < NT; nt++) {
                int c = nt * 8 + 2 * q;
                float z0 = accL[nt][0] + s_zb[c];
                float z1 = accL[nt][1] + s_zb[c + 1];
                float z2 = accL[nt][2] + s_zb[c];
                float z3 = accL[nt][3] + s_zb[c + 1];
                accL[nt][0] = z0; accL[nt][1] = z1; accL[nt][2] = z2; accL[nt][3] = z3;
                if (z0 > mA) { mA = z0; iA = c; }
                if (z1 > mA) { mA = z1; iA = c + 1; }
                if (z2 > mB) { mB = z2; iB = c; }
                if (z3 > mB) { mB = z3; iB = c + 1; }
            }
            #pragma unroll
            for (int o = 1; o <= 2; o <<= 1) {
                float ov = __shfl_xor_sync(0xffffffffu, mA, o);
                int   oi = __shfl_xor_sync(0xffffffffu, iA, o);
                if (ov > mA || (ov == mA && oi < iA)) { mA = ov; iA = oi; }
                ov = __shfl_xor_sync(0xffffffffu, mB, o);
                oi = __shfl_xor_sync(0xffffffffu, iB, o);
                if (ov > mB || (ov == mB && oi < iB)) { mB = ov; iB = oi; }
            }
            float sA = 0.f, sB2 = 0.f;
            #pragma unroll
            for (int nt = 0; nt < NT; nt++) {
                sA += __expf(accL[nt][0] - mA) + __expf(accL[nt][1] - mA);
                sB2 += __expf(accL[nt][2] - mB) + __expf(accL[nt][3] - mB);
            }
            #pragma unroll
            for (int o = 1; o <= 2; o <<= 1) {
                sA += __shfl_xor_sync(0xffffffffu, sA, o);
                sB2 += __shfl_xor_sync(0xffffffffu, sB2, o);
            }
            if (q == 0) {
                int u = row0 - NO + r;
                float scoreA = 1.0f / sA;
                int fA = 0;
                if (iA >= 16 && iA < 36 && scoreA > 0.5f) fA |= 1;
                if (iA >= 36 && scoreA > 0.3f) fA |= 2;
                g_pred[u] = iA;
                g_flags[u] = fA;
                float scoreB = 1.0f / sB2;
                int fB = 0;
                if (iB >= 16 && iB < 36 && scoreB > 0.5f) fB |= 1;
                if (iB >= 36 && scoreB > 0.3f) fB |= 2;
                g_pred[u + 8] = iB;
                g_flags[u + 8] = fB;
            }
        }
    }
    grid_sync();

    // =================== Phase 2: weighted CE epilogue ===================
    {
        if (tid == 0) { s_wsum = 0.f; s_wcnt = 0; }
        __syncthreads();

        int c1 = lane + 32;
        bool v1ok = (c1 < CNUM);
        float b0v = b[lane];
        float b1v = v1ok ? b[c1] : -1e30f;

        // 2048 warps handle 16384 u-rows: 8 per warp
        #pragma unroll 1
        for (int j = 0; j < 8; j++) {
            int u = (blockIdx.x * 8 + wid) + j * 2048;
            int f = g_flags[u];
            if (f == 0) continue;
            int pr = g_pred[u];
            const float* Pu = g_P + (size_t)(NO + u) * NCOL;
            float base0 = 0.3f * Pu[lane] + b0v;
            float base1 = v1ok ? (0.3f * Pu[c1] + b1v) : -1e30f;
            int rep_lo = (f & 1) ? 0 : 2;
            int rep_hi = (f & 1) ? 2 : 5;
            float wsum = 0.f;
            int wcnt = 0;
            for (int rep = rep_lo; rep < rep_hi; rep++) {
                int i = (rep < 2) ? idx_m[(size_t)rep * NU + u]
                                  : idx_t[(size_t)(rep - 2) * NU + u];
                const float* Pi = g_P + (size_t)i * NCOL;
                float v0 = 0.7f * Pi[lane] + base0;
                float v1z = v1ok ? (0.7f * Pi[c1] + base1) : -1e30f;
                float m = fmaxf(v0, v1z);
                #pragma unroll
                for (int o = 16; o; o >>= 1) m = fmaxf(m, __shfl_xor_sync(0xffffffffu, m, o));
                float s = __expf(v0 - m) + (v1ok ? __expf(v1z - m) : 0.f);
                #pragma unroll
                for (int o = 16; o; o >>= 1) s += __shfl_xor_sync(0xffffffffu, s, o);
                float lse = m + __logf(s);
                int lab = label[i];
                float pickl = (lab < 32) ? v0 : v1z;
                float zl = __shfl_sync(0xffffffffu, pickl, lab & 31);
                float pickp = (pr < 32) ? v0 : v1z;
                float zp = __shfl_sync(0xffffffffu, pickp, pr & 31);
                wsum += lse - 0.7f * zl - 0.3f * zp;
                wcnt += 1;
            }
            if (lane == 0 && wcnt) {
                atomicAdd(&s_wsum, wsum);
                atomicAdd(&s_wcnt, wcnt);
            }
        }
        __syncthreads();
        if (tid == 0) {
            if (s_wcnt > 0) {
                atomicAdd(&g_sum, s_wsum);
                atomicAdd(&g_cnt, s_wcnt);
            }
            __threadfence();
            unsigned t = atomicAdd(&g_done, 1u);
            if (t == GRID - 1) {
                float s = atomicAdd(&g_sum, 0.f);
                int c = atomicAdd(&g_cnt, 0);
                out[0] = s / fmaxf((float)c, 1.0f);
            }
        }
    }
}

// ---------------------------------------------------------------------------
// Launch
// ---------------------------------------------------------------------------
extern "C" void kernel_launch(void* const* d_in, const int* in_sizes, int n_in,
                              void* d_out, int out_size) {
    const float* feat  = (const float*)d_in[0];
    const int*   label = (const int*)d_in[1];
    const float* W_o = (const float*)d_in[2];
    const float* b_o = (const float*)d_in[3];
    const float* W   = (const float*)d_in[4];
    const float* b   = (const float*)d_in[5];
    // d_in[6], d_in[7]: group masks — deterministic (mid: 16<=c<36, tail: c>=36).
    const int* idx_m = (const int*)d_in[8];
    const int* idx_t = (const int*)d_in[9];
    float* out = (float*)d_out;

    static int attr_set = 0;
    if (!attr_set) {
        cudaFuncSetAttribute(fused_kernel,
                             cudaFuncAttributeMaxDynamicSharedMemorySize, SMEM_DYN);
        attr_set = 1;
    }
    fused_kernel<<<GRID, NTHR, SMEM_DYN>>>(feat, b_o, W, W_o, b, label,
                                           idx_m, idx_t, out);
}

// round 13
// speedup vs baseline: 1.3867x; 1.3867x over previous
#include <cuda_runtime.h>
#include <cuda_bf16.h>
#include <cstdint>

// ---------------------------------------------------------------------------
// Problem constants
// ---------------------------------------------------------------------------
#define NO 16384
#define NU 16384
#define DK 1024
#define CNUM 51
#define NCOL 64          // g_P row stride (padded)
#define NT 7             // n-tiles of 8 cols -> 56 >= 51
#define NK32 (DK / 32)   // 32 k-blocks of 32
#define GRID 256
#define NTHR 256

// ---------------------------------------------------------------------------
// Device scratch (static only — no cudaMalloc allowed)
// ---------------------------------------------------------------------------
__device__ __align__(16) float g_P[(NO + NU) * NCOL];   // feat @ W^T
// Fragment-packed weights (k-PERMUTED layout matching float4 A loads)
__device__ __align__(16) uint4 g_WbF[NK32 * 8 * 32];    // bf16(W)
__device__ __align__(16) uint4 g_WohF[NK32 * 8 * 32];   // hi(W_o)
__device__ __align__(16) uint4 g_WolF[NK32 * 8 * 32];   // lo(W_o)
__device__ int g_pred[NU];
__device__ int g_flags[NU];
__device__ float g_sum;
__device__ int g_cnt;
__device__ unsigned g_done;
// grid barrier state (generation-based; replay-safe)
__device__ volatile unsigned g_bar_count;
__device__ volatile unsigned g_bar_gen;

// ---------------------------------------------------------------------------
// Helpers
// ---------------------------------------------------------------------------
__device__ __forceinline__ uint32_t pack_bf16(float x, float y) {
    uint32_t r;
    asm("cvt.rn.bf16x2.f32 %0, %1, %2;" : "=r"(r) : "f"(y), "f"(x));
    return r;
}

__device__ __forceinline__ void mma16816(float* d, const uint32_t* a,
                                         uint32_t b0, uint32_t b1) {
    asm volatile(
        "mma.sync.aligned.m16n8k16.row.col.f32.bf16.bf16.f32 "
        "{%0,%1,%2,%3}, {%4,%5,%6,%7}, {%8,%9}, {%0,%1,%2,%3};"
        : "+f"(d[0]), "+f"(d[1]), "+f"(d[2]), "+f"(d[3])
        : "r"(a[0]), "r"(a[1]), "r"(a[2]), "r"(a[3]), "r"(b0), "r"(b1));
}

__device__ __forceinline__ uint32_t residue_pack(uint32_t hpk, float x, float y) {
    float hx = __uint_as_float(hpk << 16);
    float hy = __uint_as_float(hpk & 0xFFFF0000u);
    return pack_bf16(x - hx, y - hy);
}

// .cg: bypass L1 (B is consumed from smem; do not pollute L1tex)
__device__ __forceinline__ void cpa16(void* smem_dst, const void* gsrc) {
    uint32_t d = (uint32_t)__cvta_generic_to_shared(smem_dst);
    asm volatile("cp.async.cg.shared.global [%0], [%1], 16;" :: "r"(d), "l"(gsrc));
}
__device__ __forceinline__ void cpa_commit() {
    asm volatile("cp.async.commit_group;");
}

// Grid-wide barrier. Safe: grid (256) <= single-wave capacity (148 SMs x occ 2).
__device__ __forceinline__ void grid_sync() {
    __syncthreads();
    if (threadIdx.x == 0) {
        __threadfence();
        unsigned gen = g_bar_gen;
        unsigned t = atomicAdd((unsigned*)&g_bar_count, 1u);
        if (t == GRID - 1) {
            g_bar_count = 0;
            __threadfence();
            g_bar_gen = gen + 1;
        } else {
            while (g_bar_gen == gen) { __nanosleep(64); }
        }
        __threadfence();
    }
    __syncthreads();
}

// ---------------------------------------------------------------------------
// ONE fused kernel: convw -> grid_sync -> GEMM+classify -> grid_sync -> epi
// ---------------------------------------------------------------------------
#define BELEM (3 * NT * 32)   // 672 uint4 per K-block

__global__ void __launch_bounds__(256, 2) fused_kernel(
    const float* __restrict__ feat, const float* __restrict__ b_o,
    const float* __restrict__ W, const float* __restrict__ W_o,
    const float* __restrict__ b, const int* __restrict__ label,
    const int* __restrict__ idx_m, const int* __restrict__ idx_t,
    float* __restrict__ out)
{
    __shared__ uint4 sB[3][3][NT * 32];
    __shared__ float s_zb[64];
    __shared__ float s_wsum;
    __shared__ int s_wcnt;

    int tid = threadIdx.x;
    int wid = tid >> 5, lane = tid & 31;

    // =================== Phase 0: weight conversion (permuted-k pack) =======
    {
        int idx = blockIdx.x * NTHR + tid;   // 0..65535; use first 32768
        if (idx == 0) { g_sum = 0.f; g_cnt = 0; g_done = 0; }
        if (idx < 32768) {
            int q = idx & 3;
            int s = (idx >> 2) & 1;
            int K = (idx >> 3) & 31;
            int n = (idx >> 8) & 63;
            int mat = idx >> 14;         // 0: W, 1: W_o
            float4 f = make_float4(0.f, 0.f, 0.f, 0.f);
            if (n < CNUM) {
                const float* src = (mat == 0) ? W : W_o;
                f = *reinterpret_cast<const float4*>(
                        src + (size_t)n * DK + K * 32 + s * 16 + q * 4);
            }
            int t = ((n & 7) << 2) | q;
            int nt = n >> 3;
            size_t w32 = ((size_t)(K * 256 + nt * 32 + t) << 2) | (s << 1);
            if (mat == 0) {
                *reinterpret_cast<uint2*>(reinterpret_cast<uint32_t*>(g_WbF) + w32) =
                    make_uint2(pack_bf16(f.x, f.y), pack_bf16(f.z, f.w));
            } else {
                uint32_t h0 = pack_bf16(f.x, f.y);
                uint32_t h1 = pack_bf16(f.z, f.w);
                *reinterpret_cast<uint2*>(reinterpret_cast<uint32_t*>(g_WohF) + w32) =
                    make_uint2(h0, h1);
                *reinterpret_cast<uint2*>(reinterpret_cast<uint32_t*>(g_WolF) + w32) =
                    make_uint2(residue_pack(h0, f.x, f.y), residue_pack(h1, f.z, f.w));
            }
        }
    }
    grid_sync();

    // =================== Phase 1: GEMM + fused classification ===================
    {
        bool is_u = wid < 4;
        int tile = is_u ? wid : wid - 4;
        int row0 = (is_u ? NO : 0) + blockIdx.x * 64 + tile * 16;
        int r = lane >> 2;        // 0..7
        int q = lane & 3;

        if (tid < 64) s_zb[tid] = (tid < CNUM) ? b_o[tid] : -1e30f;

        // permuted-k: each lane loads float4 at k-offset 4q (contiguous)
        const float* Ap0 = feat + (size_t)(row0 + r) * DK + 4 * q;
        const float* Ap1 = Ap0 + 8 * DK;

        int m0i = tid / (NT * 32), r0i = tid - m0i * (NT * 32);
        int t1 = tid + 256;
        int m1i = t1 / (NT * 32), r1i = t1 - m1i * (NT * 32);
        int t2 = tid + 512;
        int r2i = t2 - 2 * (NT * 32);
        const uint4* g0 = (m0i == 0) ? g_WbF : (m0i == 1) ? g_WohF : g_WolF;
        const uint4* g1 = (m1i == 0) ? g_WbF : (m1i == 1) ? g_WohF : g_WolF;

        // prologue: stage B for K=0 and K=1
        cpa16(&sB[0][m0i][r0i], g0 + r0i);
        cpa16(&sB[0][m1i][r1i], g1 + r1i);
        if (t2 < BELEM) cpa16(&sB[0][2][r2i], g_WolF + r2i);
        cpa_commit();
        cpa16(&sB[1][m0i][r0i], g0 + 256 + r0i);
        cpa16(&sB[1][m1i][r1i], g1 + 256 + r1i);
        if (t2 < BELEM) cpa16(&sB[1][2][r2i], g_WolF + 256 + r2i);
        cpa_commit();

        float accP[NT][4];
        float accL[NT][4];
        #pragma unroll
        for (int nt = 0; nt < NT; nt++)
            #pragma unroll
            for (int j = 0; j < 4; j++) { accP[nt][j] = 0.f; accL[nt][j] = 0.f; }

        #pragma unroll 1
        for (int K = 0; K < NK32; K++) {
            int bsel = K % 3;
            int k0 = K * 32;

            if (K < NK32 - 1) asm volatile("cp.async.wait_group 1;");
            else             asm volatile("cp.async.wait_group 0;");
            __syncthreads();

            if (K + 2 < NK32) {
                int go = (K + 2) * 256;
                int ns = (K + 2) % 3;
                cpa16(&sB[ns][m0i][r0i], g0 + go + r0i);
                cpa16(&sB[ns][m1i][r1i], g1 + go + r1i);
                if (t2 < BELEM) cpa16(&sB[ns][2][r2i], g_WolF + go + r2i);
                cpa_commit();
            }

            // A: 4 x LDG.128 (permuted-k fragments, no shuffles)
            float4 v00 = *reinterpret_cast<const float4*>(Ap0 + k0);
            float4 v10 = *reinterpret_cast<const float4*>(Ap1 + k0);
            float4 v01 = *reinterpret_cast<const float4*>(Ap0 + k0 + 16);
            float4 v11 = *reinterpret_cast<const float4*>(Ap1 + k0 + 16);

            uint32_t ah0[4], ah1[4];
            ah0[0] = pack_bf16(v00.x, v00.y);
            ah0[1] = pack_bf16(v10.x, v10.y);
            ah0[2] = pack_bf16(v00.z, v00.w);
            ah0[3] = pack_bf16(v10.z, v10.w);
            ah1[0] = pack_bf16(v01.x, v01.y);
            ah1[1] = pack_bf16(v11.x, v11.y);
            ah1[2] = pack_bf16(v01.z, v01.w);
            ah1[3] = pack_bf16(v11.z, v11.w);

            const uint4* Bb = &sB[bsel][0][lane];
            #pragma unroll
            for (int nt = 0; nt < NT; nt++) {
                uint4 bb = Bb[nt * 32];
                mma16816(accP[nt], ah0, bb.x, bb.y);
                mma16816(accP[nt], ah1, bb.z, bb.w);
            }

            if (is_u) {
                uint32_t al0[4], al1[4];
                al0[0] = residue_pack(ah0[0], v00.x, v00.y);
                al0[1] = residue_pack(ah0[1], v10.x, v10.y);
                al0[2] = residue_pack(ah0[2], v00.z, v00.w);
                al0[3] = residue_pack(ah0[3], v10.z, v10.w);
                al1[0] = residue_pack(ah1[0], v01.x, v01.y);
                al1[1] = residue_pack(ah1[1], v11.x, v11.y);
                al1[2] = residue_pack(ah1[2], v01.z, v01.w);
                al1[3] = residue_pack(ah1[3], v11.z, v11.w);
                const uint4* Bh = &sB[bsel][1][lane];
                const uint4* Bl = &sB[bsel][2][lane];
                #pragma unroll
                for (int nt = 0; nt < NT; nt++) {
                    uint4 bh = Bh[nt * 32];
                    uint4 bl = Bl[nt * 32];
                    mma16816(accL[nt], ah0, bh.x, bh.y);   // hi*hi
                    mma16816(accL[nt], ah1, bh.z, bh.w);
                    mma16816(accL[nt], al0, bh.x, bh.y);   // lo*hi
                    mma16816(accL[nt], al1, bh.z, bh.w);
                    mma16816(accL[nt], ah0, bl.x, bl.y);   // hi*lo
                    mma16816(accL[nt], ah1, bl.z, bl.w);
                }
            }
        }

        // ---- value epilogue: store P fragments (56 cols) ----
        float* dst0 = g_P + (size_t)(row0 + r) * NCOL + 2 * q;
        float* dst1 = dst0 + 8 * NCOL;
        #pragma unroll
        for (int nt = 0; nt < NT; nt++) {
            *reinterpret_cast<float2*>(dst0 + nt * 8) = make_float2(accP[nt][0], accP[nt][1]);
            *reinterpret_cast<float2*>(dst1 + nt * 8) = make_float2(accP[nt][2], accP[nt][3]);
        }

        // ---- fused classification (u-warps): rows r (A) and r+8 (B) ----
        if (is_u) {
            float mA = -1e30f, mB = -1e30f;
            int iA = 0, iB = 0;
            #pragma unroll
            for (int nt = 0; nt < NT; nt++) {
                int c = nt * 8 + 2 * q;
                float z0 = accL[nt][0] + s_zb[c];
                float z1 = accL[nt][1] + s_zb[c + 1];
                float z2 = accL[nt][2] + s_zb[c];
                float z3 = accL[nt][3] + s_zb[c + 1];
                accL[nt][0] = z0; accL[nt][1] = z1; accL[nt][2] = z2; accL[nt][3] = z3;
                if (z0 > mA) { mA = z0; iA = c; }
                if (z1 > mA) { mA = z1; iA = c + 1; }
                if (z2 > mB) { mB = z2; iB = c; }
                if (z3 > mB) { mB = z3; iB = c + 1; }
            }
            #pragma unroll
            for (int o = 1; o <= 2; o <<= 1) {
                float ov = __shfl_xor_sync(0xffffffffu, mA, o);
                int   oi = __shfl_xor_sync(0xffffffffu, iA, o);
                if (ov > mA || (ov == mA && oi < iA)) { mA = ov; iA = oi; }
                ov = __shfl_xor_sync(0xffffffffu, mB, o);
                oi = __shfl_xor_sync(0xffffffffu, iB, o);
                if (ov > mB || (ov == mB && oi < iB)) { mB = ov; iB = oi; }
            }
            float sA = 0.f, sB2 = 0.f;
            #pragma unroll
            for (int nt = 0; nt < NT; nt++) {
                sA += __expf(accL[nt][0] - mA) + __expf(accL[nt][1] - mA);
                sB2 += __expf(accL[nt][2] - mB) + __expf(accL[nt][3] - mB);
            }
            #pragma unroll
            for (int o = 1; o <= 2; o <<= 1) {
                sA += __shfl_xor_sync(0xffffffffu, sA, o);
                sB2 += __shfl_xor_sync(0xffffffffu, sB2, o);
            }
            if (q == 0) {
                int u = row0 - NO + r;
                float scoreA = 1.0f / sA;
                int fA = 0;
                if (iA >= 16 && iA < 36 && scoreA > 0.5f) fA |= 1;
                if (iA >= 36 && scoreA > 0.3f) fA |= 2;
                g_pred[u] = iA;
                g_flags[u] = fA;
                float scoreB = 1.0f / sB2;
                int fB = 0;
                if (iB >= 16 && iB < 36 && scoreB > 0.5f) fB |= 1;
                if (iB >= 36 && scoreB > 0.3f) fB |= 2;
                g_pred[u + 8] = iB;
                g_flags[u + 8] = fB;
            }
        }
    }
    grid_sync();

    // =================== Phase 2: weighted CE epilogue ===================
    {
        if (tid == 0) { s_wsum = 0.f; s_wcnt = 0; }
        __syncthreads();

        int c1 = lane + 32;
        bool v1ok = (c1 < CNUM);
        float b0v = b[lane];
        float b1v = v1ok ? b[c1] : -1e30f;

        // 2048 warps handle 16384 u-rows: 8 per warp
        #pragma unroll 1
        for (int j = 0; j < 8; j++) {
            int u = (blockIdx.x * 8 + wid) + j * 2048;
            int f = g_flags[u];
            if (f == 0) continue;
            int pr = g_pred[u];
            const float* Pu = g_P + (size_t)(NO + u) * NCOL;
            float base0 = 0.3f * Pu[lane] + b0v;
            float base1 = v1ok ? (0.3f * Pu[c1] + b1v) : -1e30f;
            int rep_lo = (f & 1) ? 0 : 2;
            int rep_hi = (f & 1) ? 2 : 5;
            float wsum = 0.f;
            int wcnt = 0;
            for (int rep = rep_lo; rep < rep_hi; rep++) {
                int i = (rep < 2) ? idx_m[(size_t)rep * NU + u]
                                  : idx_t[(size_t)(rep - 2) * NU + u];
                const float* Pi = g_P + (size_t)i * NCOL;
                float v0 = 0.7f * Pi[lane] + base0;
                float v1z = v1ok ? (0.7f * Pi[c1] + base1) : -1e30f;
                float m = fmaxf(v0, v1z);
                #pragma unroll
                for (int o = 16; o; o >>= 1) m = fmaxf(m, __shfl_xor_sync(0xffffffffu, m, o));
                float s = __expf(v0 - m) + (v1ok ? __expf(v1z - m) : 0.f);
                #pragma unroll
                for (int o = 16; o; o >>= 1) s += __shfl_xor_sync(0xffffffffu, s, o);
                float lse = m + __logf(s);
                int lab = label[i];
                float pickl = (lab < 32) ? v0 : v1z;
                float zl = __shfl_sync(0xffffffffu, pickl, lab & 31);
                float pickp = (pr < 32) ? v0 : v1z;
                float zp = __shfl_sync(0xffffffffu, pickp, pr & 31);
                wsum += lse - 0.7f * zl - 0.3f * zp;
                wcnt += 1;
            }
            if (lane == 0 && wcnt) {
                atomicAdd(&s_wsum, wsum);
                atomicAdd(&s_wcnt, wcnt);
            }
        }
        __syncthreads();
        if (tid == 0) {
            if (s_wcnt > 0) {
                atomicAdd(&g_sum, s_wsum);
                atomicAdd(&g_cnt, s_wcnt);
            }
            __threadfence();
            unsigned t = atomicAdd(&g_done, 1u);
            if (t == GRID - 1) {
                float s = atomicAdd(&g_sum, 0.f);
                int c = atomicAdd(&g_cnt, 0);
                out[0] = s / fmaxf((float)c, 1.0f);
            }
        }
    }
}

// ---------------------------------------------------------------------------
// Launch
// ---------------------------------------------------------------------------
extern "C" void kernel_launch(void* const* d_in, const int* in_sizes, int n_in,
                              void* d_out, int out_size) {
    const float* feat  = (const float*)d_in[0];
    const int*   label = (const int*)d_in[1];
    const float* W_o = (const float*)d_in[2];
    const float* b_o = (const float*)d_in[3];
    const float* W   = (const float*)d_in[4];
    const float* b   = (const float*)d_in[5];
    // d_in[6], d_in[7]: group masks — deterministic (mid: 16<=c<36, tail: c>=36).
    const int* idx_m = (const int*)d_in[8];
    const int* idx_t = (const int*)d_in[9];
    float* out = (float*)d_out;

    fused_kernel<<<GRID, NTHR>>>(feat, b_o, W, W_o, b, label, idx_m, idx_t, out);
}

// round 14
// speedup vs baseline: 1.4916x; 1.0756x over previous
#include <cuda_runtime.h>
#include <cuda_bf16.h>
#include <cstdint>

// ---------------------------------------------------------------------------
// Problem constants
// ---------------------------------------------------------------------------
#define NO 16384
#define NU 16384
#define DK 1024
#define CNUM 51
#define NCOL 64          // g_P row stride (padded)
#define NT 7             // n-tiles of 8 cols -> 56 >= 51
#define NK32 (DK / 32)   // 32 k-blocks of 32
#define GRID 256
#define NTHR 256

// ---------------------------------------------------------------------------
// Device scratch (static only — no cudaMalloc allowed)
// ---------------------------------------------------------------------------
__device__ __align__(16) float g_P[(NO + NU) * NCOL];   // feat @ W^T
// Fragment-packed weights (k-PERMUTED layout matching float4 A loads)
__device__ __align__(16) uint4 g_WbF[NK32 * 8 * 32];    // bf16(W)
__device__ __align__(16) uint4 g_WohF[NK32 * 8 * 32];   // hi(W_o)
__device__ __align__(16) uint4 g_WolF[NK32 * 8 * 32];   // lo(W_o)
__device__ int g_pred[NU];
__device__ int g_flags[NU];
__device__ float g_sum;
__device__ int g_cnt;
__device__ unsigned g_done;
// grid barrier state (generation-based; replay-safe)
__device__ volatile unsigned g_bar_count;
__device__ volatile unsigned g_bar_gen;

// ---------------------------------------------------------------------------
// Helpers
// ---------------------------------------------------------------------------
__device__ __forceinline__ uint32_t pack_bf16(float x, float y) {
    uint32_t r;
    asm("cvt.rn.bf16x2.f32 %0, %1, %2;" : "=r"(r) : "f"(y), "f"(x));
    return r;
}

__device__ __forceinline__ void mma16816(float* d, const uint32_t* a,
                                         uint32_t b0, uint32_t b1) {
    asm volatile(
        "mma.sync.aligned.m16n8k16.row.col.f32.bf16.bf16.f32 "
        "{%0,%1,%2,%3}, {%4,%5,%6,%7}, {%8,%9}, {%0,%1,%2,%3};"
        : "+f"(d[0]), "+f"(d[1]), "+f"(d[2]), "+f"(d[3])
        : "r"(a[0]), "r"(a[1]), "r"(a[2]), "r"(a[3]), "r"(b0), "r"(b1));
}

__device__ __forceinline__ uint32_t residue_pack(uint32_t hpk, float x, float y) {
    float hx = __uint_as_float(hpk << 16);
    float hy = __uint_as_float(hpk & 0xFFFF0000u);
    return pack_bf16(x - hx, y - hy);
}

// streaming float4 load (evict-first: A rows have zero temporal reuse)
__device__ __forceinline__ float4 ldcs4(const float* p) {
    return __ldcs(reinterpret_cast<const float4*>(p));
}
// streaming float2 store (P is re-read only via L2 in phase 2)
__device__ __forceinline__ void stcs2(float* p, float2 v) {
    __stcs(reinterpret_cast<float2*>(p), v);
}

// .cg: bypass L1 (B is consumed from smem; do not pollute L1tex)
__device__ __forceinline__ void cpa16(void* smem_dst, const void* gsrc) {
    uint32_t d = (uint32_t)__cvta_generic_to_shared(smem_dst);
    asm volatile("cp.async.cg.shared.global [%0], [%1], 16;" :: "r"(d), "l"(gsrc));
}
__device__ __forceinline__ void cpa_commit() {
    asm volatile("cp.async.commit_group;");
}

// Grid-wide barrier. Safe: grid (256) <= single-wave capacity (148 SMs x occ 2).
__device__ __forceinline__ void grid_sync() {
    __syncthreads();
    if (threadIdx.x == 0) {
        __threadfence();
        unsigned gen = g_bar_gen;
        unsigned t = atomicAdd((unsigned*)&g_bar_count, 1u);
        if (t == GRID - 1) {
            g_bar_count = 0;
            __threadfence();
            g_bar_gen = gen + 1;
        } else {
            while (g_bar_gen == gen) { __nanosleep(64); }
        }
        __threadfence();
    }
    __syncthreads();
}

// ---------------------------------------------------------------------------
// ONE fused kernel: convw -> grid_sync -> GEMM+classify -> grid_sync -> epi
// ---------------------------------------------------------------------------
#define BELEM (3 * NT * 32)   // 672 uint4 per K-block

__global__ void __launch_bounds__(256, 2) fused_kernel(
    const float* __restrict__ feat, const float* __restrict__ b_o,
    const float* __restrict__ W, const float* __restrict__ W_o,
    const float* __restrict__ b, const int* __restrict__ label,
    const int* __restrict__ idx_m, const int* __restrict__ idx_t,
    float* __restrict__ out)
{
    __shared__ uint4 sB[3][3][NT * 32];
    __shared__ float s_zb[64];
    __shared__ float s_wsum;
    __shared__ int s_wcnt;

    int tid = threadIdx.x;
    int wid = tid >> 5, lane = tid & 31;

    // =================== Phase 0: weight conversion (permuted-k pack) =======
    {
        int idx = blockIdx.x * NTHR + tid;   // 0..65535; use first 32768
        if (idx == 0) { g_sum = 0.f; g_cnt = 0; g_done = 0; }
        if (idx < 32768) {
            int q = idx & 3;
            int s = (idx >> 2) & 1;
            int K = (idx >> 3) & 31;
            int n = (idx >> 8) & 63;
            int mat = idx >> 14;         // 0: W, 1: W_o
            float4 f = make_float4(0.f, 0.f, 0.f, 0.f);
            if (n < CNUM) {
                const float* src = (mat == 0) ? W : W_o;
                f = *reinterpret_cast<const float4*>(
                        src + (size_t)n * DK + K * 32 + s * 16 + q * 4);
            }
            int t = ((n & 7) << 2) | q;
            int nt = n >> 3;
            size_t w32 = ((size_t)(K * 256 + nt * 32 + t) << 2) | (s << 1);
            if (mat == 0) {
                *reinterpret_cast<uint2*>(reinterpret_cast<uint32_t*>(g_WbF) + w32) =
                    make_uint2(pack_bf16(f.x, f.y), pack_bf16(f.z, f.w));
            } else {
                uint32_t h0 = pack_bf16(f.x, f.y);
                uint32_t h1 = pack_bf16(f.z, f.w);
                *reinterpret_cast<uint2*>(reinterpret_cast<uint32_t*>(g_WohF) + w32) =
                    make_uint2(h0, h1);
                *reinterpret_cast<uint2*>(reinterpret_cast<uint32_t*>(g_WolF) + w32) =
                    make_uint2(residue_pack(h0, f.x, f.y), residue_pack(h1, f.z, f.w));
            }
        }
    }
    grid_sync();

    // =================== Phase 1: GEMM + fused classification ===================
    {
        bool is_u = wid < 4;
        int tile = is_u ? wid : wid - 4;
        int row0 = (is_u ? NO : 0) + blockIdx.x * 64 + tile * 16;
        int r = lane >> 2;        // 0..7
        int q = lane & 3;

        if (tid < 64) s_zb[tid] = (tid < CNUM) ? b_o[tid] : -1e30f;

        // permuted-k: each lane loads float4 at k-offset 4q (contiguous)
        const float* Ap0 = feat + (size_t)(row0 + r) * DK + 4 * q;
        const float* Ap1 = Ap0 + 8 * DK;

        int m0i = tid / (NT * 32), r0i = tid - m0i * (NT * 32);
        int t1 = tid + 256;
        int m1i = t1 / (NT * 32), r1i = t1 - m1i * (NT * 32);
        int t2 = tid + 512;
        int r2i = t2 - 2 * (NT * 32);
        const uint4* g0 = (m0i == 0) ? g_WbF : (m0i == 1) ? g_WohF : g_WolF;
        const uint4* g1 = (m1i == 0) ? g_WbF : (m1i == 1) ? g_WohF : g_WolF;

        // prologue: stage B for K=0 and K=1
        cpa16(&sB[0][m0i][r0i], g0 + r0i);
        cpa16(&sB[0][m1i][r1i], g1 + r1i);
        if (t2 < BELEM) cpa16(&sB[0][2][r2i], g_WolF + r2i);
        cpa_commit();
        cpa16(&sB[1][m0i][r0i], g0 + 256 + r0i);
        cpa16(&sB[1][m1i][r1i], g1 + 256 + r1i);
        if (t2 < BELEM) cpa16(&sB[1][2][r2i], g_WolF + 256 + r2i);
        cpa_commit();

        float accP[NT][4];
        float accL[NT][4];
        #pragma unroll
        for (int nt = 0; nt < NT; nt++)
            #pragma unroll
            for (int j = 0; j < 4; j++) { accP[nt][j] = 0.f; accL[nt][j] = 0.f; }

        #pragma unroll 1
        for (int K = 0; K < NK32; K++) {
            int bsel = K % 3;
            int k0 = K * 32;

            if (K < NK32 - 1) asm volatile("cp.async.wait_group 1;");
            else             asm volatile("cp.async.wait_group 0;");
            __syncthreads();

            if (K + 2 < NK32) {
                int go = (K + 2) * 256;
                int ns = (K + 2) % 3;
                cpa16(&sB[ns][m0i][r0i], g0 + go + r0i);
                cpa16(&sB[ns][m1i][r1i], g1 + go + r1i);
                if (t2 < BELEM) cpa16(&sB[ns][2][r2i], g_WolF + go + r2i);
                cpa_commit();
            }

            // A: 4 x LDG.128.CS (streaming; no L1 pollution, no reuse anyway)
            float4 v00 = ldcs4(Ap0 + k0);
            float4 v10 = ldcs4(Ap1 + k0);
            float4 v01 = ldcs4(Ap0 + k0 + 16);
            float4 v11 = ldcs4(Ap1 + k0 + 16);

            uint32_t ah0[4], ah1[4];
            ah0[0] = pack_bf16(v00.x, v00.y);
            ah0[1] = pack_bf16(v10.x, v10.y);
            ah0[2] = pack_bf16(v00.z, v00.w);
            ah0[3] = pack_bf16(v10.z, v10.w);
            ah1[0] = pack_bf16(v01.x, v01.y);
            ah1[1] = pack_bf16(v11.x, v11.y);
            ah1[2] = pack_bf16(v01.z, v01.w);
            ah1[3] = pack_bf16(v11.z, v11.w);

            const uint4* Bb = &sB[bsel][0][lane];
            #pragma unroll
            for (int nt = 0; nt < NT; nt++) {
                uint4 bb = Bb[nt * 32];
                mma16816(accP[nt], ah0, bb.x, bb.y);
                mma16816(accP[nt], ah1, bb.z, bb.w);
            }

            if (is_u) {
                uint32_t al0[4], al1[4];
                al0[0] = residue_pack(ah0[0], v00.x, v00.y);
                al0[1] = residue_pack(ah0[1], v10.x, v10.y);
                al0[2] = residue_pack(ah0[2], v00.z, v00.w);
                al0[3] = residue_pack(ah0[3], v10.z, v10.w);
                al1[0] = residue_pack(ah1[0], v01.x, v01.y);
                al1[1] = residue_pack(ah1[1], v11.x, v11.y);
                al1[2] = residue_pack(ah1[2], v01.z, v01.w);
                al1[3] = residue_pack(ah1[3], v11.z, v11.w);
                const uint4* Bh = &sB[bsel][1][lane];
                const uint4* Bl = &sB[bsel][2][lane];
                #pragma unroll
                for (int nt = 0; nt < NT; nt++) {
                    uint4 bh = Bh[nt * 32];
                    uint4 bl = Bl[nt * 32];
                    mma16816(accL[nt], ah0, bh.x, bh.y);   // hi*hi
                    mma16816(accL[nt], ah1, bh.z, bh.w);
                    mma16816(accL[nt], al0, bh.x, bh.y);   // lo*hi
                    mma16816(accL[nt], al1, bh.z, bh.w);
                    mma16816(accL[nt], ah0, bl.x, bl.y);   // hi*lo
                    mma16816(accL[nt], ah1, bl.z, bl.w);
                }
            }
        }

        // ---- value epilogue: store P fragments (56 cols, streaming) ----
        float* dst0 = g_P + (size_t)(row0 + r) * NCOL + 2 * q;
        float* dst1 = dst0 + 8 * NCOL;
        #pragma unroll
        for (int nt = 0; nt < NT; nt++) {
            stcs2(dst0 + nt * 8, make_float2(accP[nt][0], accP[nt][1]));
            stcs2(dst1 + nt * 8, make_float2(accP[nt][2], accP[nt][3]));
        }

        // ---- fused classification (u-warps): rows r (A) and r+8 (B) ----
        if (is_u) {
            float mA = -1e30f, mB = -1e30f;
            int iA = 0, iB = 0;
            #pragma unroll
            for (int nt = 0; nt < NT; nt++) {
                int c = nt * 8 + 2 * q;
                float z0 = accL[nt][0] + s_zb[c];
                float z1 = accL[nt][1] + s_zb[c + 1];
                float z2 = accL[nt][2] + s_zb[c];
                float z3 = accL[nt][3] + s_zb[c + 1];
                accL[nt][0] = z0; accL[nt][1] = z1; accL[nt][2] = z2; accL[nt][3] = z3;
                if (z0 > mA) { mA = z0; iA = c; }
                if (z1 > mA) { mA = z1; iA = c + 1; }
                if (z2 > mB) { mB = z2; iB = c; }
                if (z3 > mB) { mB = z3; iB = c + 1; }
            }
            #pragma unroll
            for (int o = 1; o <= 2; o <<= 1) {
                float ov = __shfl_xor_sync(0xffffffffu, mA, o);
                int   oi = __shfl_xor_sync(0xffffffffu, iA, o);
                if (ov > mA || (ov == mA && oi < iA)) { mA = ov; iA = oi; }
                ov = __shfl_xor_sync(0xffffffffu, mB, o);
                oi = __shfl_xor_sync(0xffffffffu, iB, o);
                if (ov > mB || (ov == mB && oi < iB)) { mB = ov; iB = oi; }
            }
            float sA = 0.f, sB2 = 0.f;
            #pragma unroll
            for (int nt = 0; nt < NT; nt++) {
                sA += __expf(accL[nt][0] - mA) + __expf(accL[nt][1] - mA);
                sB2 += __expf(accL[nt][2] - mB) + __expf(accL[nt][3] - mB);
            }
            #pragma unroll
            for (int o = 1; o <= 2; o <<= 1) {
                sA += __shfl_xor_sync(0xffffffffu, sA, o);
                sB2 += __shfl_xor_sync(0xffffffffu, sB2, o);
            }
            if (q == 0) {
                int u = row0 - NO + r;
                float scoreA = 1.0f / sA;
                int fA = 0;
                if (iA >= 16 && iA < 36 && scoreA > 0.5f) fA |= 1;
                if (iA >= 36 && scoreA > 0.3f) fA |= 2;
                g_pred[u] = iA;
                g_flags[u] = fA;
                float scoreB = 1.0f / sB2;
                int fB = 0;
                if (iB >= 16 && iB < 36 && scoreB > 0.5f) fB |= 1;
                if (iB >= 36 && scoreB > 0.3f) fB |= 2;
                g_pred[u + 8] = iB;
                g_flags[u + 8] = fB;
            }
        }
    }
    grid_sync();

    // =================== Phase 2: weighted CE epilogue ===================
    {
        if (tid == 0) { s_wsum = 0.f; s_wcnt = 0; }
        __syncthreads();

        int c1 = lane + 32;
        bool v1ok = (c1 < CNUM);
        float b0v = b[lane];
        float b1v = v1ok ? b[c1] : -1e30f;

        // 2048 warps handle 16384 u-rows: 8 per warp
        #pragma unroll 1
        for (int j = 0; j < 8; j++) {
            int u = (blockIdx.x * 8 + wid) + j * 2048;
            int f = g_flags[u];
            if (f == 0) continue;
            int pr = g_pred[u];
            const float* Pu = g_P + (size_t)(NO + u) * NCOL;
            float base0 = 0.3f * Pu[lane] + b0v;
            float base1 = v1ok ? (0.3f * Pu[c1] + b1v) : -1e30f;
            int rep_lo = (f & 1) ? 0 : 2;
            int rep_hi = (f & 1) ? 2 : 5;
            float wsum = 0.f;
            int wcnt = 0;
            for (int rep = rep_lo; rep < rep_hi; rep++) {
                int i = (rep < 2) ? idx_m[(size_t)rep * NU + u]
                                  : idx_t[(size_t)(rep - 2) * NU + u];
                const float* Pi = g_P + (size_t)i * NCOL;
                float v0 = 0.7f * Pi[lane] + base0;
                float v1z = v1ok ? (0.7f * Pi[c1] + base1) : -1e30f;
                float m = fmaxf(v0, v1z);
                #pragma unroll
                for (int o = 16; o; o >>= 1) m = fmaxf(m, __shfl_xor_sync(0xffffffffu, m, o));
                float s = __expf(v0 - m) + (v1ok ? __expf(v1z - m) : 0.f);
                #pragma unroll
                for (int o = 16; o; o >>= 1) s += __shfl_xor_sync(0xffffffffu, s, o);
                float lse = m + __logf(s);
                int lab = label[i];
                float pickl = (lab < 32) ? v0 : v1z;
                float zl = __shfl_sync(0xffffffffu, pickl, lab & 31);
                float pickp = (pr < 32) ? v0 : v1z;
                float zp = __shfl_sync(0xffffffffu, pickp, pr & 31);
                wsum += lse - 0.7f * zl - 0.3f * zp;
                wcnt += 1;
            }
            if (lane == 0 && wcnt) {
                atomicAdd(&s_wsum, wsum);
                atomicAdd(&s_wcnt, wcnt);
            }
        }
        __syncthreads();
        if (tid == 0) {
            if (s_wcnt > 0) {
                atomicAdd(&g_sum, s_wsum);
                atomicAdd(&g_cnt, s_wcnt);
            }
            __threadfence();
            unsigned t = atomicAdd(&g_done, 1u);
            if (t == GRID - 1) {
                float s = atomicAdd(&g_sum, 0.f);
                int c = atomicAdd(&g_cnt, 0);
                out[0] = s / fmaxf((float)c, 1.0f);
            }
        }
    }
}

// ---------------------------------------------------------------------------
// Launch
// ---------------------------------------------------------------------------
extern "C" void kernel_launch(void* const* d_in, const int* in_sizes, int n_in,
                              void* d_out, int out_size) {
    const float* feat  = (const float*)d_in[0];
    const int*   label = (const int*)d_in[1];
    const float* W_o = (const float*)d_in[2];
    const float* b_o = (const float*)d_in[3];
    const float* W   = (const float*)d_in[4];
    const float* b   = (const float*)d_in[5];
    // d_in[6], d_in[7]: group masks — deterministic (mid: 16<=c<36, tail: c>=36).
    const int* idx_m = (const int*)d_in[8];
    const int* idx_t = (const int*)d_in[9];
    float* out = (float*)d_out;

    fused_kernel<<<GRID, NTHR>>>(feat, b_o, W, W_o, b, label, idx_m, idx_t, out);
}